// round 3
// baseline (speedup 1.0000x reference)
#include <cuda_runtime.h>

#define B_ 64
#define T_ 800
#define J_ 50
#define D_ 200

constexpr int TPB1 = 128;
constexpr int NW   = 4;      // warps per block
constexpr int TT   = 8;      // t-rows per warp
constexpr int TBLK = NW * TT;    // 32 t-rows per block
constexpr int UPITCH4 = 51;      // float4 per u row (204 words; 204%32=12 -> conflict-free)
constexpr int D4 = D_ / 4;       // 50
constexpr int NCHUNK = 25;       // T chunks for q2c partial reduction (800/32)

// scratch (no cudaMalloc allowed)
__device__ float  g_m[B_ * T_];
__device__ float2 g_MS[B_];                        // (max, sum) per batch
__device__ float  g_part[B_ * NCHUNK * D_];        // q2c partials
__device__ __align__(16) float g_q2c[B_ * D_];

// ---- packed f32x2 helpers ----
__device__ __forceinline__ void fma2(unsigned long long& d, unsigned long long a, unsigned long long b) {
    asm("fma.rn.f32x2 %0, %1, %2, %0;" : "+l"(d) : "l"(a), "l"(b));
}
__device__ __forceinline__ float2 unpack2(unsigned long long v) {
    float2 r; asm("mov.b64 {%0, %1}, %2;" : "=f"(r.x), "=f"(r.y) : "l"(v)); return r;
}
__device__ __forceinline__ float warpSum(float v) {
    #pragma unroll
    for (int o = 16; o > 0; o >>= 1) v += __shfl_xor_sync(0xffffffffu, v, o);
    return v;
}
__device__ __forceinline__ float warpMax(float v) {
    #pragma unroll
    for (int o = 16; o > 0; o >>= 1) v = fmaxf(v, __shfl_xor_sync(0xffffffffu, v, o));
    return v;
}

// =====================================================================
// K1: per (b, t): s row, softmax over J, c2q, write out[:, 0:600], emit m[b,t]
// smem: u_s (40800B) + hw_s (4 warps * 8 t * 200 * 4 = 25600B) + su_s (200B)
// 'a' (softmax weights) overlays the owning warp's hw region after phase B.
// =====================================================================
__global__ __launch_bounds__(TPB1, 3) void bidaf_k1(
    const float* __restrict__ h, const float* __restrict__ u,
    const float* __restrict__ w_h, const float* __restrict__ b_h,
    const float* __restrict__ w_u, const float* __restrict__ b_u,
    const float* __restrict__ w_hu, const float* __restrict__ b_hu,
    float* __restrict__ out)
{
    extern __shared__ char smem_raw[];
    float* u_s  = (float*)smem_raw;                  // J_ * UPITCH4*4 floats
    float* hw_s = u_s + J_ * UPITCH4 * 4;            // NW * TT * D_
    float* su_s = hw_s + NW * TT * D_;               // J_

    const int b   = blockIdx.y;
    const int t0  = blockIdx.x * TBLK;
    const int tid = threadIdx.x;
    const int warp = tid >> 5, lane = tid & 31;

    const float4* u4g = (const float4*)u;
    const float4* h4g = (const float4*)h;
    float4* us4 = (float4*)u_s;

    // ---- load u[b] tile into smem ----
    for (int idx = tid; idx < J_ * UPITCH4; idx += TPB1) {
        int j = idx / UPITCH4, k = idx - j * UPITCH4;
        if (k < D4) us4[j * UPITCH4 + k] = u4g[(b * J_ + j) * D4 + k];
    }
    const float bias = b_h[0] + b_u[0] + b_hu[0];
    __syncthreads();

    // ---- su_s[j] = dot(u_j, w_u) + bias ----
    const float4* wu4 = (const float4*)w_u;
    for (int j = warp; j < J_; j += NW) {
        float acc = 0.f;
        for (int k = lane; k < D4; k += 32) {
            float4 a = us4[j * UPITCH4 + k], w = wu4[k];
            acc += a.x * w.x + a.y * w.y + a.z * w.z + a.w * w.w;
        }
        acc = warpSum(acc);
        if (lane == 0) su_s[j] = acc + bias;
    }
    __syncthreads();

    // ---- phase A: hw = h * w_hu (to smem), sh = dot(h, w_h) ----
    const float4* whu4 = (const float4*)w_hu;
    const float4* wh4  = (const float4*)w_h;
    float4* hw4 = (float4*)hw_s;
    const int tw = t0 + warp * TT;
    float sh[TT];
    #pragma unroll
    for (int tt = 0; tt < TT; tt++) {
        int t = tw + tt;
        long rb = (long)(b * T_ + t) * D4;
        float4 a = h4g[rb + lane];
        float4 w1 = whu4[lane];
        hw4[warp * (TT * D4) + tt * D4 + lane] =
            make_float4(a.x * w1.x, a.y * w1.y, a.z * w1.z, a.w * w1.w);
        float4 w2 = wh4[lane];
        float p = a.x * w2.x + a.y * w2.y + a.z * w2.z + a.w * w2.w;
        if (lane < D4 - 32) {
            float4 a2 = h4g[rb + 32 + lane];
            float4 w1b = whu4[32 + lane];
            hw4[warp * (TT * D4) + tt * D4 + 32 + lane] =
                make_float4(a2.x * w1b.x, a2.y * w1b.y, a2.z * w1b.z, a2.w * w1b.w);
            float4 w2b = wh4[32 + lane];
            p += a2.x * w2b.x + a2.y * w2b.y + a2.z * w2b.z + a2.w * w2b.w;
        }
        sh[tt] = warpSum(p);
    }
    __syncwarp();

    // ---- phase B: s[t, j] = sum_d hw[d] * u[j, d] ; lane-per-j (j0=lane, j1=lane+32) ----
    const bool jv = (lane < J_ - 32);   // lane < 18: second j-slot valid
    unsigned long long acc[TT][2];
    #pragma unroll
    for (int tt = 0; tt < TT; tt++) { acc[tt][0] = 0ull; acc[tt][1] = 0ull; }

    const ulonglong2* usU = (const ulonglong2*)u_s;
    const ulonglong2* hwU = (const ulonglong2*)hw_s;
    const int j0 = lane, j1 = lane + 32;

    #pragma unroll 2
    for (int k = 0; k < D4; k++) {
        ulonglong2 U0 = usU[j0 * UPITCH4 + k];
        ulonglong2 U1; U1.x = 0ull; U1.y = 0ull;
        if (jv) U1 = usU[j1 * UPITCH4 + k];
        #pragma unroll
        for (int tt = 0; tt < TT; tt++) {
            ulonglong2 Hb = hwU[warp * (TT * D4) + tt * D4 + k];  // broadcast
            fma2(acc[tt][0], U0.x, Hb.x);
            fma2(acc[tt][0], U0.y, Hb.y);
            fma2(acc[tt][1], U1.x, Hb.x);
            fma2(acc[tt][1], U1.y, Hb.y);
        }
    }

    // ---- softmax over j; store a (duplicated pairs) overlaying own hw region ----
    float2* a2w = (float2*)(hw_s + warp * (TT * D_));   // warp-private overlay
    const float su0 = su_s[j0];
    const float su1 = jv ? su_s[j1] : -1e30f;
    #pragma unroll
    for (int tt = 0; tt < TT; tt++) {
        float2 p0 = unpack2(acc[tt][0]);
        float2 p1 = unpack2(acc[tt][1]);
        float s0 = p0.x + p0.y + sh[tt] + su0;
        float s1 = p1.x + p1.y + sh[tt] + su1;
        float mx = warpMax(fmaxf(s0, s1));
        float e0 = __expf(s0 - mx);
        float e1 = __expf(s1 - mx);
        float sm = warpSum(e0 + e1);
        float inv = 1.f / sm;
        float a0 = e0 * inv, a1 = e1 * inv;
        a2w[tt * 52 + j0] = make_float2(a0, a0);
        if (jv) a2w[tt * 52 + j1] = make_float2(a1, a1);
        if (lane == 0) g_m[b * T_ + (tw + tt)] = mx;
    }
    __syncwarp();

    // ---- c2q[t, d] = sum_j a[t,j] * u[j,d] ; lane-per-d4-chunk ----
    unsigned long long cacc[TT][2][2];
    #pragma unroll
    for (int tt = 0; tt < TT; tt++)
        #pragma unroll
        for (int c = 0; c < 2; c++) { cacc[tt][c][0] = 0ull; cacc[tt][c][1] = 0ull; }

    const bool v1 = (lane < D4 - 32);
    const int k0 = lane, k1 = 32 + lane;
    #pragma unroll 2
    for (int j = 0; j < J_; j++) {
        ulonglong2 Ua = usU[j * UPITCH4 + k0];
        ulonglong2 Ub; Ub.x = 0ull; Ub.y = 0ull;
        if (v1) Ub = usU[j * UPITCH4 + k1];
        #pragma unroll
        for (int tt = 0; tt < TT; tt++) {
            unsigned long long aj = *(const unsigned long long*)&a2w[tt * 52 + j]; // broadcast
            fma2(cacc[tt][0][0], aj, Ua.x);
            fma2(cacc[tt][0][1], aj, Ua.y);
            fma2(cacc[tt][1][0], aj, Ub.x);
            fma2(cacc[tt][1][1], aj, Ub.y);
        }
    }

    // ---- epilogue: out[b,t, 0:200]=h, [200:400]=c2q, [400:600]=h*c2q ----
    #pragma unroll
    for (int tt = 0; tt < TT; tt++) {
        int t = tw + tt;
        long rb = (long)(b * T_ + t) * D4;
        float4* o4 = (float4*)out + (long)(b * T_ + t) * (4 * D4);
        float4 ha = h4g[rb + lane];
        float2 ca = unpack2(cacc[tt][0][0]);
        float2 cb = unpack2(cacc[tt][0][1]);
        float4 c0 = make_float4(ca.x, ca.y, cb.x, cb.y);
        o4[lane]        = ha;
        o4[50 + lane]   = c0;
        o4[100 + lane]  = make_float4(ha.x * c0.x, ha.y * c0.y, ha.z * c0.z, ha.w * c0.w);
        if (v1) {
            float4 hb2 = h4g[rb + k1];
            float2 cc = unpack2(cacc[tt][1][0]);
            float2 cd = unpack2(cacc[tt][1][1]);
            float4 c1 = make_float4(cc.x, cc.y, cd.x, cd.y);
            o4[k1]        = hb2;
            o4[50 + k1]   = c1;
            o4[100 + k1]  = make_float4(hb2.x * c1.x, hb2.y * c1.y, hb2.z * c1.z, hb2.w * c1.w);
        }
    }
}

// =====================================================================
// K2m: per b, compute M = max_t m[b,t], S = sum_t exp(m-M)
// =====================================================================
__global__ __launch_bounds__(256) void bidaf_k2m()
{
    __shared__ float red[8];
    const int b = blockIdx.x, tid = threadIdx.x;
    const int warp = tid >> 5, lane = tid & 31;

    float mx = -3.0e38f;
    for (int i = tid; i < T_; i += 256) mx = fmaxf(mx, g_m[b * T_ + i]);
    mx = warpMax(mx);
    if (lane == 0) red[warp] = mx;
    __syncthreads();
    float M = red[0];
    #pragma unroll
    for (int i = 1; i < 8; i++) M = fmaxf(M, red[i]);
    __syncthreads();

    float se = 0.f;
    for (int i = tid; i < T_; i += 256) se += __expf(g_m[b * T_ + i] - M);
    se = warpSum(se);
    if (lane == 0) red[warp] = se;
    __syncthreads();
    if (tid == 0) {
        float S = 0.f;
        #pragma unroll
        for (int i = 0; i < 8; i++) S += red[i];
        g_MS[b] = make_float2(M, S);
    }
}

// =====================================================================
// K2b: partial q2c: block (chunk c, batch b) sums 32 t's weighted by exp(m-M)
// =====================================================================
__global__ __launch_bounds__(256) void bidaf_k2b(const float* __restrict__ h)
{
    __shared__ float ws[32];
    const int c = blockIdx.x, b = blockIdx.y, tid = threadIdx.x;
    const float M = g_MS[b].x;
    if (tid < 32) ws[tid] = __expf(g_m[b * T_ + c * 32 + tid] - M);
    __syncthreads();
    if (tid < D_) {
        const float* hp = h + ((long)b * T_ + c * 32) * D_ + tid;
        float acc = 0.f;
        #pragma unroll
        for (int t = 0; t < 32; t++) acc += ws[t] * hp[t * D_];
        g_part[(b * NCHUNK + c) * D_ + tid] = acc;
    }
}

// =====================================================================
// K2c: combine partials, divide by S
// =====================================================================
__global__ __launch_bounds__(256) void bidaf_k2c()
{
    const int b = blockIdx.x, tid = threadIdx.x;
    if (tid < D_) {
        float acc = 0.f;
        #pragma unroll
        for (int c = 0; c < NCHUNK; c++) acc += g_part[(b * NCHUNK + c) * D_ + tid];
        g_q2c[b * D_ + tid] = acc / g_MS[b].y;
    }
}

// =====================================================================
// K3: out[b,t, 600:800] = h[b,t,:] * q2c[b,:]
// =====================================================================
__global__ __launch_bounds__(256) void bidaf_k3(const float* __restrict__ h,
                                                float* __restrict__ out)
{
    int idx = blockIdx.x * blockDim.x + threadIdx.x;  // float4 index into h
    if (idx >= B_ * T_ * D4) return;
    int d4 = idx % D4;
    int bt = idx / D4;
    int b  = bt / T_;
    float4 hv = ((const float4*)h)[idx];
    float4 q  = ((const float4*)g_q2c)[b * D4 + d4];
    ((float4*)out)[(long)bt * (4 * D4) + 150 + d4] =
        make_float4(hv.x * q.x, hv.y * q.y, hv.z * q.z, hv.w * q.w);
}

// =====================================================================
extern "C" void kernel_launch(void* const* d_in, const int* in_sizes, int n_in,
                              void* d_out, int out_size)
{
    const float* h    = (const float*)d_in[0];
    const float* u    = (const float*)d_in[1];
    const float* w_h  = (const float*)d_in[2];
    const float* b_h  = (const float*)d_in[3];
    const float* w_u  = (const float*)d_in[4];
    const float* b_u  = (const float*)d_in[5];
    const float* w_hu = (const float*)d_in[6];
    const float* b_hu = (const float*)d_in[7];
    float* out = (float*)d_out;

    constexpr int SMEM1 = (J_ * UPITCH4 * 4 + NW * TT * D_ + J_) * 4;  // 66600 B
    cudaFuncSetAttribute(bidaf_k1, cudaFuncAttributeMaxDynamicSharedMemorySize, SMEM1);

    bidaf_k1<<<dim3(T_ / TBLK, B_), TPB1, SMEM1>>>(h, u, w_h, b_h, w_u, b_u, w_hu, b_hu, out);
    bidaf_k2m<<<B_, 256>>>();
    bidaf_k2b<<<dim3(NCHUNK, B_), 256>>>(h);
    bidaf_k2c<<<B_, 256>>>();
    bidaf_k3<<<(B_ * T_ * D4 + 255) / 256, 256>>>(h, out);
}

// round 4
// speedup vs baseline: 1.1178x; 1.1178x over previous
#include <cuda_runtime.h>

#define B_ 64
#define T_ 800
#define J_ 50
#define D_ 200

constexpr int TPB1 = 256;
constexpr int NW   = 8;      // warps per block
constexpr int TT   = 4;      // t-rows per warp
constexpr int TBLK = NW * TT;    // 32 t-rows per block
constexpr int UPITCH4 = 51;      // float4 per u row (204 words; 204%32=12 -> conflict-free)
constexpr int D4 = D_ / 4;       // 50
constexpr int NCHUNK = 25;       // = T_/TBLK

// scratch (no cudaMalloc allowed)
__device__ float2 g_cm[B_ * NCHUNK];            // (chunk max, chunk expsum)
__device__ float  g_part[B_ * NCHUNK * D_];     // unnormalized q2c partials

// ---- packed f32x2 helpers ----
__device__ __forceinline__ void fma2(unsigned long long& d, unsigned long long a, unsigned long long b) {
    asm("fma.rn.f32x2 %0, %1, %2, %0;" : "+l"(d) : "l"(a), "l"(b));
}
__device__ __forceinline__ float2 unpack2(unsigned long long v) {
    float2 r; asm("mov.b64 {%0, %1}, %2;" : "=f"(r.x), "=f"(r.y) : "l"(v)); return r;
}
__device__ __forceinline__ float warpSum(float v) {
    #pragma unroll
    for (int o = 16; o > 0; o >>= 1) v += __shfl_xor_sync(0xffffffffu, v, o);
    return v;
}
__device__ __forceinline__ float warpMax(float v) {
    #pragma unroll
    for (int o = 16; o > 0; o >>= 1) v = fmaxf(v, __shfl_xor_sync(0xffffffffu, v, o));
    return v;
}

// =====================================================================
// K1: per (b, 32 t-rows): s row, softmax over J, c2q, out[:,0:600],
//     plus chunk-local q2c partial (max, expsum, weighted h-sum).
// smem: u_s (40800B) + hw_s (25600B) + su_s (200B) + m_s/es_s (256B)
// =====================================================================
__global__ __launch_bounds__(TPB1, 3) void bidaf_k1(
    const float* __restrict__ h, const float* __restrict__ u,
    const float* __restrict__ w_h, const float* __restrict__ b_h,
    const float* __restrict__ w_u, const float* __restrict__ b_u,
    const float* __restrict__ w_hu, const float* __restrict__ b_hu,
    float* __restrict__ out)
{
    extern __shared__ char smem_raw[];
    float* u_s  = (float*)smem_raw;                  // J_ * UPITCH4*4 floats
    float* hw_s = u_s + J_ * UPITCH4 * 4;            // NW * TT * D_
    float* su_s = hw_s + NW * TT * D_;               // J_
    float* m_s  = su_s + J_ + 2;                     // TBLK
    float* es_s = m_s + TBLK;                        // TBLK

    const int b   = blockIdx.y;
    const int c   = blockIdx.x;
    const int t0  = c * TBLK;
    const int tid = threadIdx.x;
    const int warp = tid >> 5, lane = tid & 31;

    const float4* u4g = (const float4*)u;
    const float4* h4g = (const float4*)h;
    float4* us4 = (float4*)u_s;

    // ---- load u[b] tile into smem ----
    for (int idx = tid; idx < J_ * UPITCH4; idx += TPB1) {
        int j = idx / UPITCH4, k = idx - j * UPITCH4;
        if (k < D4) us4[j * UPITCH4 + k] = u4g[(b * J_ + j) * D4 + k];
    }
    const float bias = b_h[0] + b_u[0] + b_hu[0];
    __syncthreads();

    // ---- su_s[j] = dot(u_j, w_u) + bias ----
    const float4* wu4 = (const float4*)w_u;
    for (int j = warp; j < J_; j += NW) {
        float acc = 0.f;
        for (int k = lane; k < D4; k += 32) {
            float4 a = us4[j * UPITCH4 + k], w = wu4[k];
            acc += a.x * w.x + a.y * w.y + a.z * w.z + a.w * w.w;
        }
        acc = warpSum(acc);
        if (lane == 0) su_s[j] = acc + bias;
    }
    __syncthreads();

    // ---- phase A: hw = h * w_hu (to smem), sh = dot(h, w_h) ----
    const float4* whu4 = (const float4*)w_hu;
    const float4* wh4  = (const float4*)w_h;
    float4* hw4 = (float4*)hw_s;
    const int tw = t0 + warp * TT;
    float sh[TT];
    #pragma unroll
    for (int tt = 0; tt < TT; tt++) {
        int t = tw + tt;
        long rb = (long)(b * T_ + t) * D4;
        float4 a = h4g[rb + lane];
        float4 w1 = whu4[lane];
        hw4[warp * (TT * D4) + tt * D4 + lane] =
            make_float4(a.x * w1.x, a.y * w1.y, a.z * w1.z, a.w * w1.w);
        float4 w2 = wh4[lane];
        float p = a.x * w2.x + a.y * w2.y + a.z * w2.z + a.w * w2.w;
        if (lane < D4 - 32) {
            float4 a2 = h4g[rb + 32 + lane];
            float4 w1b = whu4[32 + lane];
            hw4[warp * (TT * D4) + tt * D4 + 32 + lane] =
                make_float4(a2.x * w1b.x, a2.y * w1b.y, a2.z * w1b.z, a2.w * w1b.w);
            float4 w2b = wh4[32 + lane];
            p += a2.x * w2b.x + a2.y * w2b.y + a2.z * w2b.z + a2.w * w2b.w;
        }
        sh[tt] = warpSum(p);
    }
    __syncwarp();

    // ---- phase B: s[t, j] = sum_d hw[d] * u[j, d] ; lane-per-j ----
    const bool jv = (lane < J_ - 32);   // lane < 18: second j-slot valid
    unsigned long long acc[TT][2];
    #pragma unroll
    for (int tt = 0; tt < TT; tt++) { acc[tt][0] = 0ull; acc[tt][1] = 0ull; }

    const ulonglong2* usU = (const ulonglong2*)u_s;
    const ulonglong2* hwU = (const ulonglong2*)hw_s;
    const int j0 = lane, j1 = lane + 32;

    #pragma unroll 2
    for (int k = 0; k < D4; k++) {
        ulonglong2 U0 = usU[j0 * UPITCH4 + k];
        ulonglong2 U1; U1.x = 0ull; U1.y = 0ull;
        if (jv) U1 = usU[j1 * UPITCH4 + k];
        #pragma unroll
        for (int tt = 0; tt < TT; tt++) {
            ulonglong2 Hb = hwU[warp * (TT * D4) + tt * D4 + k];  // broadcast
            fma2(acc[tt][0], U0.x, Hb.x);
            fma2(acc[tt][0], U0.y, Hb.y);
            fma2(acc[tt][1], U1.x, Hb.x);
            fma2(acc[tt][1], U1.y, Hb.y);
        }
    }

    // ---- softmax over j; store a (duplicated pairs) overlaying own hw region ----
    float2* a2w = (float2*)(hw_s + warp * (TT * D_));   // warp-private overlay
    const float su0 = su_s[j0];
    const float su1 = jv ? su_s[j1] : -1e30f;
    #pragma unroll
    for (int tt = 0; tt < TT; tt++) {
        float2 p0 = unpack2(acc[tt][0]);
        float2 p1 = unpack2(acc[tt][1]);
        float s0 = p0.x + p0.y + sh[tt] + su0;
        float s1 = p1.x + p1.y + sh[tt] + su1;
        float mx = warpMax(fmaxf(s0, s1));
        float e0 = __expf(s0 - mx);
        float e1 = __expf(s1 - mx);
        float sm = warpSum(e0 + e1);
        float inv = 1.f / sm;
        float a0 = e0 * inv, a1 = e1 * inv;
        a2w[tt * 52 + j0] = make_float2(a0, a0);
        if (jv) a2w[tt * 52 + j1] = make_float2(a1, a1);
        if (lane == 0) m_s[warp * TT + tt] = mx;
    }
    __syncwarp();

    // ---- c2q[t, d] = sum_j a[t,j] * u[j,d] ; lane-per-d4-chunk ----
    unsigned long long cacc[TT][2][2];
    #pragma unroll
    for (int tt = 0; tt < TT; tt++)
        #pragma unroll
        for (int cc = 0; cc < 2; cc++) { cacc[tt][cc][0] = 0ull; cacc[tt][cc][1] = 0ull; }

    const bool v1 = (lane < D4 - 32);
    const int k0 = lane, k1 = 32 + lane;
    for (int j = 0; j < J_; j++) {
        ulonglong2 Ua = usU[j * UPITCH4 + k0];
        ulonglong2 Ub; Ub.x = 0ull; Ub.y = 0ull;
        if (v1) Ub = usU[j * UPITCH4 + k1];
        #pragma unroll
        for (int tt = 0; tt < TT; tt++) {
            unsigned long long aj = *(const unsigned long long*)&a2w[tt * 52 + j]; // broadcast
            fma2(cacc[tt][0][0], aj, Ua.x);
            fma2(cacc[tt][0][1], aj, Ua.y);
            fma2(cacc[tt][1][0], aj, Ub.x);
            fma2(cacc[tt][1][1], aj, Ub.y);
        }
    }

    // ---- epilogue: out[b,t, 0:200]=h, [200:400]=c2q, [400:600]=h*c2q ----
    #pragma unroll
    for (int tt = 0; tt < TT; tt++) {
        int t = tw + tt;
        long rb = (long)(b * T_ + t) * D4;
        float4* o4 = (float4*)out + (long)(b * T_ + t) * (4 * D4);
        float4 ha = h4g[rb + lane];
        float2 ca = unpack2(cacc[tt][0][0]);
        float2 cb = unpack2(cacc[tt][0][1]);
        float4 c0 = make_float4(ca.x, ca.y, cb.x, cb.y);
        o4[lane]        = ha;
        o4[50 + lane]   = c0;
        o4[100 + lane]  = make_float4(ha.x * c0.x, ha.y * c0.y, ha.z * c0.z, ha.w * c0.w);
        if (v1) {
            float4 hb2 = h4g[rb + k1];
            float2 cc2 = unpack2(cacc[tt][1][0]);
            float2 cd = unpack2(cacc[tt][1][1]);
            float4 c1 = make_float4(cc2.x, cc2.y, cd.x, cd.y);
            o4[k1]        = hb2;
            o4[50 + k1]   = c1;
            o4[100 + k1]  = make_float4(hb2.x * c1.x, hb2.y * c1.y, hb2.z * c1.z, hb2.w * c1.w);
        }
    }

    // ---- chunk-local q2c partial: m_c, s_c, sum_t exp(m_t-m_c)*h[t,:] ----
    __syncthreads();
    if (warp == 0) {
        float mv = (lane < TBLK) ? m_s[lane] : -3.0e38f;
        float mc = warpMax(mv);
        float ev = (lane < TBLK) ? __expf(mv - mc) : 0.f;
        float sc = warpSum(ev);
        if (lane < TBLK) es_s[lane] = ev;
        if (lane == 0) g_cm[b * NCHUNK + c] = make_float2(mc, sc);
    }
    __syncthreads();
    if (tid < D_) {
        const float* hp = h + ((long)b * T_ + t0) * D_ + tid;
        float a0 = 0.f, a1 = 0.f, a2 = 0.f, a3 = 0.f;
        #pragma unroll
        for (int t = 0; t < TBLK; t += 4) {
            a0 += es_s[t]     * hp[t * D_];
            a1 += es_s[t + 1] * hp[(t + 1) * D_];
            a2 += es_s[t + 2] * hp[(t + 2) * D_];
            a3 += es_s[t + 3] * hp[(t + 3) * D_];
        }
        g_part[(b * NCHUNK + c) * D_ + tid] = (a0 + a1) + (a2 + a3);
    }
}

// =====================================================================
// K3: combine chunk records -> q2c[b,:], write out[b,t,600:800] = h*q2c
// grid (8, B_): each block handles 100 t-rows of batch b
// =====================================================================
__global__ __launch_bounds__(256) void bidaf_k3(const float* __restrict__ h,
                                                float* __restrict__ out)
{
    __shared__ float ws[32];
    __shared__ __align__(16) float qs[D_];
    __shared__ float Ss;
    const int b = blockIdx.y, tseg = blockIdx.x, tid = threadIdx.x;

    if (tid < 32) {
        float2 cm = (tid < NCHUNK) ? g_cm[b * NCHUNK + tid] : make_float2(-3.0e38f, 0.f);
        float M = warpMax(cm.x);
        float e = (tid < NCHUNK) ? __expf(cm.x - M) : 0.f;
        float S = warpSum(e * cm.y);
        ws[tid] = e;
        if (tid == 0) Ss = S;
    }
    __syncthreads();
    if (tid < D_) {
        float acc = 0.f;
        #pragma unroll
        for (int c2 = 0; c2 < NCHUNK; c2++)
            acc += ws[c2] * g_part[(b * NCHUNK + c2) * D_ + tid];
        qs[tid] = acc / Ss;
    }
    __syncthreads();

    const float4* q4 = (const float4*)qs;
    const int t0 = tseg * (T_ / 8);
    for (int idx = tid; idx < (T_ / 8) * D4; idx += 256) {
        int t = idx / D4, d4 = idx % D4;
        long bt = (long)b * T_ + t0 + t;
        float4 hv = ((const float4*)h)[bt * D4 + d4];
        float4 q  = q4[d4];
        ((float4*)out)[bt * (4 * D4) + 150 + d4] =
            make_float4(hv.x * q.x, hv.y * q.y, hv.z * q.z, hv.w * q.w);
    }
}

// =====================================================================
extern "C" void kernel_launch(void* const* d_in, const int* in_sizes, int n_in,
                              void* d_out, int out_size)
{
    const float* h    = (const float*)d_in[0];
    const float* u    = (const float*)d_in[1];
    const float* w_h  = (const float*)d_in[2];
    const float* b_h  = (const float*)d_in[3];
    const float* w_u  = (const float*)d_in[4];
    const float* b_u  = (const float*)d_in[5];
    const float* w_hu = (const float*)d_in[6];
    const float* b_hu = (const float*)d_in[7];
    float* out = (float*)d_out;

    constexpr int SMEM1 = (J_ * UPITCH4 * 4 + NW * TT * D_ + J_ + 2 + 2 * TBLK) * 4;
    cudaFuncSetAttribute(bidaf_k1, cudaFuncAttributeMaxDynamicSharedMemorySize, SMEM1);

    bidaf_k1<<<dim3(NCHUNK, B_), TPB1, SMEM1>>>(h, u, w_h, b_h, w_u, b_u, w_hu, b_hu, out);
    bidaf_k3<<<dim3(8, B_), 256>>>(h, out);
}

// round 5
// speedup vs baseline: 1.1879x; 1.0627x over previous
#include <cuda_runtime.h>

#define B_ 64
#define T_ 800
#define J_ 50
#define D_ 200

constexpr int TPB1 = 256;
constexpr int NW   = 8;      // warps per block
constexpr int TT   = 4;      // t-rows per warp
constexpr int TBLK = NW * TT;    // 32 t-rows per block
constexpr int UPITCH4 = 51;      // float4 per u row (204 words; 204%32=12 -> conflict-free)
constexpr int D4 = D_ / 4;       // 50
constexpr int NCHUNK = 25;       // = T_/TBLK

// scratch (no cudaMalloc allowed)
__device__ float2 g_cm[B_ * NCHUNK];            // (chunk max, chunk expsum)
__device__ float  g_part[B_ * NCHUNK * D_];     // unnormalized q2c partials

// ---- packed f32x2 helpers ----
__device__ __forceinline__ void fma2(unsigned long long& d, unsigned long long a, unsigned long long b) {
    asm("fma.rn.f32x2 %0, %1, %2, %0;" : "+l"(d) : "l"(a), "l"(b));
}
__device__ __forceinline__ float2 unpack2(unsigned long long v) {
    float2 r; asm("mov.b64 {%0, %1}, %2;" : "=f"(r.x), "=f"(r.y) : "l"(v)); return r;
}
__device__ __forceinline__ float warpSum(float v) {
    #pragma unroll
    for (int o = 16; o > 0; o >>= 1) v += __shfl_xor_sync(0xffffffffu, v, o);
    return v;
}
__device__ __forceinline__ float warpMax(float v) {
    #pragma unroll
    for (int o = 16; o > 0; o >>= 1) v = fmaxf(v, __shfl_xor_sync(0xffffffffu, v, o));
    return v;
}

// =====================================================================
// K1: per (b, 32 t-rows): s row, softmax over J, c2q, out[:,0:600],
//     plus chunk-local q2c partial (max, expsum, weighted h-sum).
// =====================================================================
__global__ __launch_bounds__(TPB1, 3) void bidaf_k1(
    const float* __restrict__ h, const float* __restrict__ u,
    const float* __restrict__ w_h, const float* __restrict__ b_h,
    const float* __restrict__ w_u, const float* __restrict__ b_u,
    const float* __restrict__ w_hu, const float* __restrict__ b_hu,
    float* __restrict__ out)
{
    extern __shared__ char smem_raw[];
    float* u_s  = (float*)smem_raw;                  // J_ * UPITCH4*4 floats
    float* hw_s = u_s + J_ * UPITCH4 * 4;            // NW * TT * D_
    float* su_s = hw_s + NW * TT * D_;               // J_
    float* m_s  = su_s + J_ + 2;                     // TBLK
    float* es_s = m_s + TBLK;                        // TBLK

    const int b   = blockIdx.y;
    const int c   = blockIdx.x;
    const int t0  = c * TBLK;
    const int tid = threadIdx.x;
    const int warp = tid >> 5, lane = tid & 31;

    const float4* u4g = (const float4*)u;
    const float4* h4g = (const float4*)h;
    float4* us4 = (float4*)u_s;

    // ---- load u[b] tile into smem ----
    for (int idx = tid; idx < J_ * UPITCH4; idx += TPB1) {
        int j = idx / UPITCH4, k = idx - j * UPITCH4;
        if (k < D4) us4[j * UPITCH4 + k] = u4g[(b * J_ + j) * D4 + k];
    }
    const float bias = b_h[0] + b_u[0] + b_hu[0];
    __syncthreads();

    // ---- su_s[j] = dot(u_j, w_u) + bias ----
    const float4* wu4 = (const float4*)w_u;
    for (int j = warp; j < J_; j += NW) {
        float acc = 0.f;
        for (int k = lane; k < D4; k += 32) {
            float4 a = us4[j * UPITCH4 + k], w = wu4[k];
            acc += a.x * w.x + a.y * w.y + a.z * w.z + a.w * w.w;
        }
        acc = warpSum(acc);
        if (lane == 0) su_s[j] = acc + bias;
    }
    __syncthreads();

    // ---- phase A: hw = h * w_hu (to smem), sh = dot(h, w_h) ----
    const float4* whu4 = (const float4*)w_hu;
    const float4* wh4  = (const float4*)w_h;
    float4* hw4 = (float4*)hw_s + warp * (TT * D4);
    const int tw = t0 + warp * TT;
    float sh[TT];
    #pragma unroll
    for (int tt = 0; tt < TT; tt++) {
        int t = tw + tt;
        long rb = (long)(b * T_ + t) * D4;
        float4 a = h4g[rb + lane];
        float4 w1 = whu4[lane];
        hw4[tt * D4 + lane] =
            make_float4(a.x * w1.x, a.y * w1.y, a.z * w1.z, a.w * w1.w);
        float4 w2 = wh4[lane];
        float p = a.x * w2.x + a.y * w2.y + a.z * w2.z + a.w * w2.w;
        if (lane < D4 - 32) {
            float4 a2 = h4g[rb + 32 + lane];
            float4 w1b = whu4[32 + lane];
            hw4[tt * D4 + 32 + lane] =
                make_float4(a2.x * w1b.x, a2.y * w1b.y, a2.z * w1b.z, a2.w * w1b.w);
            float4 w2b = wh4[32 + lane];
            p += a2.x * w2b.x + a2.y * w2b.y + a2.z * w2b.z + a2.w * w2b.w;
        }
        sh[tt] = warpSum(p);
    }
    __syncwarp();

    // ---- phase B: s[t, j] = sum_d hw[d] * u[j, d] ; lane-per-j ----
    const bool jv = (lane < J_ - 32);   // lane < 18: second j-slot valid
    unsigned long long acc[TT][2];
    #pragma unroll
    for (int tt = 0; tt < TT; tt++) { acc[tt][0] = 0ull; acc[tt][1] = 0ull; }

    const ulonglong2* usU = (const ulonglong2*)u_s;
    const ulonglong2* hwW = (const ulonglong2*)hw_s + warp * (TT * D4);
    const int j0 = lane, j1 = lane + 32;
    const ulonglong2* uj0 = usU + j0 * UPITCH4;
    const ulonglong2* uj1 = usU + j1 * UPITCH4;

    #pragma unroll 2
    for (int k = 0; k < D4; k++) {
        ulonglong2 U0 = uj0[k];
        ulonglong2 U1; U1.x = 0ull; U1.y = 0ull;
        if (jv) U1 = uj1[k];
        #pragma unroll
        for (int tt = 0; tt < TT; tt++) {
            ulonglong2 Hb = hwW[tt * D4 + k];  // broadcast
            fma2(acc[tt][0], U0.x, Hb.x);
            fma2(acc[tt][0], U0.y, Hb.y);
            fma2(acc[tt][1], U1.x, Hb.x);
            fma2(acc[tt][1], U1.y, Hb.y);
        }
    }

    // ---- softmax over j; store a (duplicated pairs) overlaying own hw region ----
    float2* a2w = (float2*)(hw_s + warp * (TT * D_));   // warp-private overlay
    const float su0 = su_s[j0];
    const float su1 = jv ? su_s[j1] : -1e30f;
    #pragma unroll
    for (int tt = 0; tt < TT; tt++) {
        float2 p0 = unpack2(acc[tt][0]);
        float2 p1 = unpack2(acc[tt][1]);
        float s0 = p0.x + p0.y + sh[tt] + su0;
        float s1 = p1.x + p1.y + sh[tt] + su1;
        float mx = warpMax(fmaxf(s0, s1));
        float e0 = __expf(s0 - mx);
        float e1 = __expf(s1 - mx);
        float sm = warpSum(e0 + e1);
        float inv = 1.f / sm;
        float a0 = e0 * inv, a1 = e1 * inv;
        a2w[tt * 52 + j0] = make_float2(a0, a0);
        if (jv) a2w[tt * 52 + j1] = make_float2(a1, a1);
        if (lane == 0) m_s[warp * TT + tt] = mx;
    }
    __syncwarp();

    // ---- c2q[t, d] = sum_j a[t,j] * u[j,d] ; lane-per-d4-chunk ----
    unsigned long long cacc[TT][2][2];
    #pragma unroll
    for (int tt = 0; tt < TT; tt++)
        #pragma unroll
        for (int cc = 0; cc < 2; cc++) { cacc[tt][cc][0] = 0ull; cacc[tt][cc][1] = 0ull; }

    const bool v1 = (lane < D4 - 32);
    const int k0 = lane, k1 = 32 + lane;
    const ulonglong2* uk0 = usU + k0;
    const ulonglong2* uk1 = usU + k1;
    #pragma unroll 2
    for (int j = 0; j < J_; j++) {
        ulonglong2 Ua = uk0[j * UPITCH4];
        ulonglong2 Ub; Ub.x = 0ull; Ub.y = 0ull;
        if (v1) Ub = uk1[j * UPITCH4];
        #pragma unroll
        for (int tt = 0; tt < TT; tt++) {
            unsigned long long aj = *(const unsigned long long*)&a2w[tt * 52 + j]; // broadcast
            fma2(cacc[tt][0][0], aj, Ua.x);
            fma2(cacc[tt][0][1], aj, Ua.y);
            fma2(cacc[tt][1][0], aj, Ub.x);
            fma2(cacc[tt][1][1], aj, Ub.y);
        }
    }

    // ---- epilogue: out[b,t, 0:200]=h, [200:400]=c2q, [400:600]=h*c2q ----
    // streaming stores (cs): keep h/u resident in L2 for K3
    #pragma unroll
    for (int tt = 0; tt < TT; tt++) {
        int t = tw + tt;
        long rb = (long)(b * T_ + t) * D4;
        float4* o4 = (float4*)out + (long)(b * T_ + t) * (4 * D4);
        float4 ha = h4g[rb + lane];
        float2 ca = unpack2(cacc[tt][0][0]);
        float2 cb = unpack2(cacc[tt][0][1]);
        float4 c0 = make_float4(ca.x, ca.y, cb.x, cb.y);
        __stcs(o4 + lane, ha);
        __stcs(o4 + 50 + lane, c0);
        __stcs(o4 + 100 + lane,
               make_float4(ha.x * c0.x, ha.y * c0.y, ha.z * c0.z, ha.w * c0.w));
        if (v1) {
            float4 hb2 = h4g[rb + k1];
            float2 cc2 = unpack2(cacc[tt][1][0]);
            float2 cd = unpack2(cacc[tt][1][1]);
            float4 c1 = make_float4(cc2.x, cc2.y, cd.x, cd.y);
            __stcs(o4 + k1, hb2);
            __stcs(o4 + 50 + k1, c1);
            __stcs(o4 + 100 + k1,
                   make_float4(hb2.x * c1.x, hb2.y * c1.y, hb2.z * c1.z, hb2.w * c1.w));
        }
    }

    // ---- chunk-local q2c partial: m_c, s_c, sum_t exp(m_t-m_c)*h[t,:] ----
    __syncthreads();
    if (warp == 0) {
        float mv = (lane < TBLK) ? m_s[lane] : -3.0e38f;
        float mc = warpMax(mv);
        float ev = (lane < TBLK) ? __expf(mv - mc) : 0.f;
        float sc = warpSum(ev);
        if (lane < TBLK) es_s[lane] = ev;
        if (lane == 0) g_cm[b * NCHUNK + c] = make_float2(mc, sc);
    }
    __syncthreads();
    if (tid < D_) {
        const float* hp = h + ((long)b * T_ + t0) * D_ + tid;
        float a0 = 0.f, a1 = 0.f, a2 = 0.f, a3 = 0.f;
        #pragma unroll
        for (int t = 0; t < TBLK; t += 4) {
            a0 += es_s[t]     * hp[t * D_];
            a1 += es_s[t + 1] * hp[(t + 1) * D_];
            a2 += es_s[t + 2] * hp[(t + 2) * D_];
            a3 += es_s[t + 3] * hp[(t + 3) * D_];
        }
        g_part[(b * NCHUNK + c) * D_ + tid] = (a0 + a1) + (a2 + a3);
    }
}

// =====================================================================
// K3: combine chunk records -> q2c[b,:], write out[b,t,600:800] = h*q2c
// grid (25, B_): each block handles 32 t-rows of batch b
// =====================================================================
__global__ __launch_bounds__(256) void bidaf_k3(const float* __restrict__ h,
                                                float* __restrict__ out)
{
    __shared__ float ws[32];
    __shared__ __align__(16) float qs[D_];
    __shared__ float Ss;
    const int b = blockIdx.y, tseg = blockIdx.x, tid = threadIdx.x;

    if (tid < 32) {
        float2 cm = (tid < NCHUNK) ? g_cm[b * NCHUNK + tid] : make_float2(-3.0e38f, 0.f);
        float M = warpMax(cm.x);
        float e = (tid < NCHUNK) ? __expf(cm.x - M) : 0.f;
        float S = warpSum(e * cm.y);
        ws[tid] = e;
        if (tid == 0) Ss = S;
    }
    __syncthreads();
    if (tid < D_) {
        float acc = 0.f;
        #pragma unroll
        for (int c2 = 0; c2 < NCHUNK; c2++)
            acc += ws[c2] * g_part[(b * NCHUNK + c2) * D_ + tid];
        qs[tid] = acc / Ss;
    }
    __syncthreads();

    const float4* q4 = (const float4*)qs;
    const int t0 = tseg * TBLK;
    // 32 t-rows * 50 float4 = 1600 float4 over 256 threads
    #pragma unroll
    for (int r = 0; r < (TBLK * D4) / 256 + 1; r++) {
        int idx = r * 256 + tid;
        if (idx < TBLK * D4) {
            int t = idx / D4, d4 = idx - (idx / D4) * D4;
            long bt = (long)b * T_ + t0 + t;
            float4 hv = __ldg(((const float4*)h) + bt * D4 + d4);
            float4 q  = q4[d4];
            __stcs(((float4*)out) + bt * (4 * D4) + 150 + d4,
                   make_float4(hv.x * q.x, hv.y * q.y, hv.z * q.z, hv.w * q.w));
        }
    }
}

// =====================================================================
extern "C" void kernel_launch(void* const* d_in, const int* in_sizes, int n_in,
                              void* d_out, int out_size)
{
    const float* h    = (const float*)d_in[0];
    const float* u    = (const float*)d_in[1];
    const float* w_h  = (const float*)d_in[2];
    const float* b_h  = (const float*)d_in[3];
    const float* w_u  = (const float*)d_in[4];
    const float* b_u  = (const float*)d_in[5];
    const float* w_hu = (const float*)d_in[6];
    const float* b_hu = (const float*)d_in[7];
    float* out = (float*)d_out;

    constexpr int SMEM1 = (J_ * UPITCH4 * 4 + NW * TT * D_ + J_ + 2 + 2 * TBLK) * 4;
    cudaFuncSetAttribute(bidaf_k1, cudaFuncAttributeMaxDynamicSharedMemorySize, SMEM1);

    bidaf_k1<<<dim3(NCHUNK, B_), TPB1, SMEM1>>>(h, u, w_h, b_h, w_u, b_u, w_hu, b_hu, out);
    bidaf_k3<<<dim3(NCHUNK, B_), 256>>>(h, out);
}